// round 14
// baseline (speedup 1.0000x reference)
#include <cuda_runtime.h>
#include <cstdint>
#include <cfloat>

// Sparsemax over rows of 16384 x 4096 fp32.
// Persistent CTAs, shared double buffer, 3 barriers/row, schedule:
//   [store row i-1] -> [prefetch row i+1] -> [wait row i] ->
//   [max pass] B1 [zero-atomic gather] B2 [warp0 solve] B3
// Stores precede the wait so store traffic covers load latency; prefetch
// is issued at the top so it has a full iteration of lead with only two
// buffers (the same-thread LDS->STG->cp.async register dependency makes
// the buffer WAR safe). Gather uses ballot/popc compaction into per-warp
// candidate segments: no shared atomics anywhere.
// Exact tau: candidates {x > rowmax-1} + Michelot (iterate 1 fused via
// per-warp sums); full-row fallback on any segment overflow.

#define N_COLS   4096
#define THREADS  256
#define NWARPS   8
#define CPW      128            // candidate cap per warp
#define NBLOCKS  (152 * 6)      // one persistent wave, 6 CTAs/SM

__device__ __forceinline__ unsigned enc_f(float f) {
    unsigned u = __float_as_uint(f);
    return (u & 0x80000000u) ? ~u : (u | 0x80000000u);   // order-preserving
}
__device__ __forceinline__ float dec_f(unsigned e) {
    unsigned u = (e & 0x80000000u) ? (e & 0x7fffffffu) : ~e;
    return __uint_as_float(u);
}

__device__ __forceinline__ void cp_row(float* dst, const float* src, int tid) {
    uint32_t s = (uint32_t)__cvta_generic_to_shared(dst);
    const float4* g = reinterpret_cast<const float4*>(src);
#pragma unroll
    for (int k = 0; k < 4; k++) {
        asm volatile("cp.async.cg.shared.global [%0], [%1], 16;\n"
                     :: "r"(s + (uint32_t)(tid + k * THREADS) * 16u),
                        "l"(g + tid + k * THREADS));
    }
}

__global__ __launch_bounds__(THREADS, 6)
void sparsemax_kernel(const float* __restrict__ x, float* __restrict__ out,
                      int rows) {
    __shared__ float    buf[2][N_COLS];      // 32 KB
    __shared__ float    cand[NWARPS][CPW];   // 4 KB per-warp segments
    __shared__ unsigned warp_max[NWARPS];
    __shared__ int      warp_cnt[NWARPS];
    __shared__ float    warp_sum[NWARPS];
    __shared__ float    sh_tau;

    const int tid    = threadIdx.x;
    const int lane   = tid & 31;
    const int wid    = tid >> 5;
    const int stride = gridDim.x;
    const unsigned lt_mask = (1u << lane) - 1u;

    const int r0 = blockIdx.x;
    if (r0 < rows) cp_row(buf[0], x + (size_t)r0 * N_COLS, tid);
    asm volatile("cp.async.commit_group;\n" ::: "memory");

    float tau_prev = 0.0f;
    int p = 0, it = 0, r;
    for (r = r0; r < rows; r += stride, p ^= 1, it++) {
        // ---- step 1: store row i-1 from buf[p^1] (own slice, tau_prev) ----
        if (it > 0) {
            const float4* bp = reinterpret_cast<const float4*>(buf[p ^ 1]);
            float4* orow = reinterpret_cast<float4*>(out + (size_t)(r - stride) * N_COLS);
#pragma unroll
            for (int k = 0; k < 4; k++) {
                float4 w = bp[tid + k * THREADS];
                float4 o;
                o.x = fmaxf(w.x - tau_prev, 0.0f);
                o.y = fmaxf(w.y - tau_prev, 0.0f);
                o.z = fmaxf(w.z - tau_prev, 0.0f);
                o.w = fmaxf(w.w - tau_prev, 0.0f);
                __stcs(&orow[tid + k * THREADS], o);
            }
        }

        // ---- step 2: prefetch row i+1 into buf[p^1] ----
        // (safe WAR: the LDS->register->STG chain above strictly precedes
        //  these cp.async issues; slices are thread-private both ways)
        const int rn = r + stride;
        if (rn < rows) cp_row(buf[p ^ 1], x + (size_t)rn * N_COLS, tid);
        asm volatile("cp.async.commit_group;\n" ::: "memory");

        // ---- step 3: wait for row i (issued one full iteration ago) ----
        asm volatile("cp.async.wait_group 1;\n" ::: "memory");

        // ---- step 4: max pass on own slice ----
        const float4* b = reinterpret_cast<const float4*>(buf[p]);
        float4 v[4];
        float m = -FLT_MAX;
#pragma unroll
        for (int k = 0; k < 4; k++) {
            v[k] = b[tid + k * THREADS];
            m = fmaxf(m, fmaxf(fmaxf(v[k].x, v[k].y), fmaxf(v[k].z, v[k].w)));
        }
        unsigned we = __reduce_max_sync(0xffffffffu, enc_f(m));
        if (lane == 0) warp_max[wid] = we;
        __syncthreads();                                     // B1

        unsigned me = warp_max[0];
#pragma unroll
        for (int i = 1; i < NWARPS; i++) me = me > warp_max[i] ? me : warp_max[i];
        const float thresh = dec_f(me) - 1.0f;               // tau* >= thresh

        // ---- step 5: zero-atomic gather into per-warp segments + S,C ----
        float s_part = 0.0f;
        int   base   = 0;      // running candidate count of this warp
#pragma unroll
        for (int k = 0; k < 4; k++) {
            float vals[4] = {v[k].x, v[k].y, v[k].z, v[k].w};
#pragma unroll
            for (int j = 0; j < 4; j++) {
                bool pred = vals[j] > thresh;
                unsigned mk = __ballot_sync(0xffffffffu, pred);
                if (pred) {
                    int pos = base + __popc(mk & lt_mask);
                    s_part += vals[j];
                    if (pos < CPW) cand[wid][pos] = vals[j];
                }
                base += __popc(mk);
            }
        }
#pragma unroll
        for (int o = 16; o > 0; o >>= 1)
            s_part += __shfl_xor_sync(0xffffffffu, s_part, o);
        if (lane == 0) { warp_sum[wid] = s_part; warp_cnt[wid] = base; }
        __syncthreads();                                     // B2

        // ---- step 6: warp 0 solves tau (others proceed to B3) ----
        if (wid == 0) {
            int   c8 = (lane < NWARPS) ? warp_cnt[lane] : 0;
            float s8 = (lane < NWARPS) ? warp_sum[lane] : 0.0f;
            const int C = __reduce_add_sync(0xffffffffu, c8);
            float S = s8;
#pragma unroll
            for (int o = 16; o > 0; o >>= 1)
                S += __shfl_xor_sync(0xffffffffu, S, o);
            const bool ovf = __any_sync(0xffffffffu, c8 > CPW);

            float t = (S - 1.0f) / (float)C;   // Michelot iterate 1 (S,C exact)
            int c_prev = C;
            if (!ovf) {
                for (;;) {
                    float s = 0.0f;
                    int   c = 0;
#pragma unroll
                    for (int w = 0; w < NWARPS; w++) {
                        int nw = warp_cnt[w];
                        for (int i = lane; i < nw; i += 32) {
                            float z = cand[w][i];
                            if (z > t) { s += z; c++; }
                        }
                    }
#pragma unroll
                    for (int o = 16; o > 0; o >>= 1)
                        s += __shfl_xor_sync(0xffffffffu, s, o);
                    c = __reduce_add_sync(0xffffffffu, c);
                    if (c == c_prev) break;     // support stabilized -> exact
                    t = (s - 1.0f) / (float)c;  // c >= 1 (rowmax in support)
                    c_prev = c;
                }
            } else {
                // full-row Michelot from shared (rare, exact); all threads'
                // cp.async completed before B1, visible since B2.
                const float* src = buf[p];
                for (;;) {
                    float s = 0.0f;
                    int   c = 0;
                    for (int i = lane; i < N_COLS; i += 32) {
                        float z = src[i];
                        if (z > t) { s += z; c++; }
                    }
#pragma unroll
                    for (int o = 16; o > 0; o >>= 1)
                        s += __shfl_xor_sync(0xffffffffu, s, o);
                    c = __reduce_add_sync(0xffffffffu, c);
                    if (c == c_prev) break;
                    t = (s - 1.0f) / (float)c;
                    c_prev = c;
                }
            }
            if (lane == 0) sh_tau = t;
        }
        __syncthreads();                                     // B3
        tau_prev = sh_tau;
    }

    // ---- epilogue: store the final processed row ----
    if (r0 < rows) {
        const int rl = r - stride;                  // last processed row
        const float4* bp = reinterpret_cast<const float4*>(buf[p ^ 1]);
        float4* orow = reinterpret_cast<float4*>(out + (size_t)rl * N_COLS);
#pragma unroll
        for (int k = 0; k < 4; k++) {
            float4 w = bp[tid + k * THREADS];
            float4 o;
            o.x = fmaxf(w.x - tau_prev, 0.0f);
            o.y = fmaxf(w.y - tau_prev, 0.0f);
            o.z = fmaxf(w.z - tau_prev, 0.0f);
            o.w = fmaxf(w.w - tau_prev, 0.0f);
            __stcs(&orow[tid + k * THREADS], o);
        }
    }
}

extern "C" void kernel_launch(void* const* d_in, const int* in_sizes, int n_in,
                              void* d_out, int out_size) {
    const float* x = (const float*)d_in[0];
    float* out = (float*)d_out;
    const int rows = in_sizes[0] / N_COLS;   // 16384
    sparsemax_kernel<<<NBLOCKS, THREADS>>>(x, out, rows);
}

// round 15
// speedup vs baseline: 1.4440x; 1.4440x over previous
#include <cuda_runtime.h>
#include <cstdint>
#include <cfloat>

// Sparsemax over rows of 16384 x 4096 fp32.
// Persistent CTAs; next row prefetched via cp.async (LDGSTS) into a shared
// double buffer. Row read from shared ONCE into registers; output written
// from registers. Exact sort-free tau:
//   candidates {x > rowmax-1} (true support always a subset),
//   Michelot iterate 1 fused into the gather (block S,C -> t1=(S-1)/C),
//   warp 0 runs the tiny residual fixed point and broadcasts tau.
// THREE barriers per row: own-slice reads are ordered by each thread's own
// cp.async.wait_group, so no barrier is needed between wait and the max
// pass. Parity-buffered block state; every cross-iteration shared write is
// separated from its last reader by an intervening __syncthreads.
// Full-row fallback from shared on candidate overflow.

#define N_COLS      4096
#define THREADS     256
#define CAND_CAP    1024
#define CTAS_PER_SM 6
#define NBLOCKS     (152 * CTAS_PER_SM)   // one persistent wave on GB300

__device__ __forceinline__ unsigned enc_f(float f) {
    unsigned u = __float_as_uint(f);
    return (u & 0x80000000u) ? ~u : (u | 0x80000000u);   // order-preserving
}
__device__ __forceinline__ float dec_f(unsigned e) {
    unsigned u = (e & 0x80000000u) ? (e & 0x7fffffffu) : ~e;
    return __uint_as_float(u);
}

__global__ __launch_bounds__(THREADS, CTAS_PER_SM)
void sparsemax_kernel(const float* __restrict__ x, float* __restrict__ out,
                      int rows) {
    __shared__ float    buf[2][N_COLS];     // 32 KB double buffer
    __shared__ float    cand[CAND_CAP];     // 4 KB
    __shared__ unsigned sh_maxbits[2];      // parity-buffered block state
    __shared__ int      sh_cnt[2];
    __shared__ float    sh_sum[2];
    __shared__ float    sh_tau;

    const int tid    = threadIdx.x;
    const int lane   = tid & 31;
    const int wid    = tid >> 5;
    const int stride = gridDim.x;

    // ---- prologue: init both state slots, prefetch first row ----
    if (tid == 0) {
        sh_maxbits[0] = 0u; sh_maxbits[1] = 0u;
        sh_cnt[0] = 0;      sh_cnt[1] = 0;
        sh_sum[0] = 0.0f;   sh_sum[1] = 0.0f;
    }
    __syncthreads();   // state visible before the first atomics

    int r0 = blockIdx.x;
    if (r0 < rows) {
        const float4* g = reinterpret_cast<const float4*>(x + (size_t)r0 * N_COLS);
        uint32_t s = (uint32_t)__cvta_generic_to_shared(&buf[0][0]);
#pragma unroll
        for (int k = 0; k < 4; k++) {
            uint32_t saddr = s + (uint32_t)(tid + k * THREADS) * 16u;
            asm volatile("cp.async.cg.shared.global [%0], [%1], 16;\n"
                         :: "r"(saddr), "l"(g + tid + k * THREADS));
        }
    }
    asm volatile("cp.async.commit_group;\n" ::: "memory");

    int p = 0;
    for (int r = r0; r < rows; r += stride, p ^= 1) {
        // ---- prefetch row i+1 into buf[p^1] (overlaps this row's tau) ----
        const int rn = r + stride;
        if (rn < rows) {
            const float4* g = reinterpret_cast<const float4*>(x + (size_t)rn * N_COLS);
            uint32_t s = (uint32_t)__cvta_generic_to_shared(&buf[p ^ 1][0]);
#pragma unroll
            for (int k = 0; k < 4; k++) {
                uint32_t saddr = s + (uint32_t)(tid + k * THREADS) * 16u;
                asm volatile("cp.async.cg.shared.global [%0], [%1], 16;\n"
                             :: "r"(saddr), "l"(g + tid + k * THREADS));
            }
        }
        asm volatile("cp.async.commit_group;\n" ::: "memory");

        // wait for OWN slice of row i (each thread reads only what its own
        // cp.async wrote -> per-thread wait is sufficient; no barrier here)
        asm volatile("cp.async.wait_group 1;\n" ::: "memory");

        const float4* b = reinterpret_cast<const float4*>(&buf[p][0]);

        // ---- single shared read: row into registers; REDUX warp max ----
        float4 v[4];
        float m = -FLT_MAX;
#pragma unroll
        for (int k = 0; k < 4; k++) {
            v[k] = b[tid + k * THREADS];
            m = fmaxf(m, fmaxf(fmaxf(v[k].x, v[k].y), fmaxf(v[k].z, v[k].w)));
        }
        unsigned we = __reduce_max_sync(0xffffffffu, enc_f(m));
        if (lane == 0) atomicMax(&sh_maxbits[p], we);
        __syncthreads();                                     // B_max
        // (B_max also publishes every thread's completed cp.async slice of
        //  buf[p] for the fallback reader below.)

        const float thresh = dec_f(sh_maxbits[p]) - 1.0f;   // tau* >= thresh

        // reset slot p^1 for its next use: all its readers finished before
        // B4 of the previous iteration (< B_max here); its next writers
        // run after the NEXT iteration's B_max.
        if (tid == 0) {
            sh_maxbits[p ^ 1] = 0u;
            sh_cnt[p ^ 1] = 0;
            sh_sum[p ^ 1] = 0.0f;
        }

        // ---- gather candidates + fused Michelot iteration 1 (S, C) ----
        float s_part = 0.0f;
#pragma unroll
        for (int k = 0; k < 4; k++) {
            float vals[4] = {v[k].x, v[k].y, v[k].z, v[k].w};
#pragma unroll
            for (int j = 0; j < 4; j++) {
                if (vals[j] > thresh) {
                    s_part += vals[j];
                    int q = atomicAdd(&sh_cnt[p], 1);
                    if (q < CAND_CAP) cand[q] = vals[j];
                }
            }
        }
#pragma unroll
        for (int o = 16; o > 0; o >>= 1)
            s_part += __shfl_xor_sync(0xffffffffu, s_part, o);
        if (lane == 0) atomicAdd(&sh_sum[p], s_part);
        __syncthreads();                                     // B_gather

        // ---- warp 0 only: residual Michelot (usually 1 short iteration) ----
        if (wid == 0) {
            const int   C = sh_cnt[p];                 // exact even on overflow
            const float S = sh_sum[p];                 // exact even on overflow
            const float* src = cand;
            int nn = C;
            if (C > CAND_CAP) { nn = N_COLS; src = &buf[p][0]; }  // rare, exact
            float t = (S - 1.0f) / (float)C;           // Michelot iterate 1
            int c_prev = C;
            for (;;) {
                float s = 0.0f;
                int   c = 0;
                for (int i = lane; i < nn; i += 32) {
                    float z = src[i];
                    if (z > t) { s += z; c++; }
                }
#pragma unroll
                for (int o = 16; o > 0; o >>= 1)
                    s += __shfl_xor_sync(0xffffffffu, s, o);
                c = __reduce_add_sync(0xffffffffu, c);
                if (c == c_prev) break;        // support stabilized -> exact tau
                t = (s - 1.0f) / (float)c;     // c >= 1 (rowmax in support)
                c_prev = c;
            }
            if (lane == 0) sh_tau = t;
        }
        __syncthreads();                                     // B_tau
        const float tau = sh_tau;

        // ---- output straight from registers, streaming stores ----
        float4* orow = reinterpret_cast<float4*>(out + (size_t)r * N_COLS);
#pragma unroll
        for (int k = 0; k < 4; k++) {
            float4 o;
            o.x = fmaxf(v[k].x - tau, 0.0f);
            o.y = fmaxf(v[k].y - tau, 0.0f);
            o.z = fmaxf(v[k].z - tau, 0.0f);
            o.w = fmaxf(v[k].w - tau, 0.0f);
            __stcs(&orow[tid + k * THREADS], o);
        }
    }
}

extern "C" void kernel_launch(void* const* d_in, const int* in_sizes, int n_in,
                              void* d_out, int out_size) {
    const float* x = (const float*)d_in[0];
    float* out = (float*)d_out;
    const int rows = in_sizes[0] / N_COLS;   // 16384
    sparsemax_kernel<<<NBLOCKS, THREADS>>>(x, out, rows);
}

// round 17
// speedup vs baseline: 1.4658x; 1.0151x over previous
#include <cuda_runtime.h>
#include <cstdint>
#include <cfloat>

// Sparsemax over rows of 16384 x 4096 fp32.
// Persistent CTAs; next row prefetched via cp.async (LDGSTS) into a shared
// double buffer. Row read from shared ONCE into registers; output written
// from registers. Exact sort-free tau:
//   candidates {x > rowmax-1} (true support always a subset),
//   Michelot iterate 1 fused into the gather (block S,C -> t1=(S-1)/C),
//   warp 0 runs the tiny residual fixed point and broadcasts tau.
// NEW: co-resident-CTA phase stagger. Wave-1 placement is round-robin, so
// CTAs bid, bid+152, ... share an SM and start in lockstep; identical
// per-row work keeps them phase-locked, alternating all-load / all-compute
// windows (DRAM idles in the latter -> the measured 65% plateau). A one-time
// __nanosleep of slot*(~row_period/6) interleaves their phases.
// Full-row fallback from shared on candidate overflow.

#define N_COLS      4096
#define THREADS     256
#define CAND_CAP    1024
#define CTAS_PER_SM 6
#define NSMS        152
#define NBLOCKS     (NSMS * CTAS_PER_SM)   // one persistent wave on GB300
#define STAGGER_NS  800u                   // ~ (row period) / 6

__device__ __forceinline__ unsigned enc_f(float f) {
    unsigned u = __float_as_uint(f);
    return (u & 0x80000000u) ? ~u : (u | 0x80000000u);   // order-preserving
}
__device__ __forceinline__ float dec_f(unsigned e) {
    unsigned u = (e & 0x80000000u) ? (e & 0x7fffffffu) : ~e;
    return __uint_as_float(u);
}

__global__ __launch_bounds__(THREADS, CTAS_PER_SM)
void sparsemax_kernel(const float* __restrict__ x, float* __restrict__ out,
                      int rows) {
    __shared__ float    buf[2][N_COLS];     // 32 KB double buffer
    __shared__ float    cand[CAND_CAP];     // 4 KB
    __shared__ unsigned sh_maxbits[2];      // parity-buffered block state
    __shared__ int      sh_cnt[2];
    __shared__ float    sh_sum[2];
    __shared__ float    sh_tau;

    const int tid    = threadIdx.x;
    const int lane   = tid & 31;
    const int wid    = tid >> 5;
    const int stride = gridDim.x;

    // ---- phase stagger: desynchronize co-resident CTAs (one-time) ----
    {
        const unsigned slot = (unsigned)(blockIdx.x / NSMS);   // 0..5
        if (slot) __nanosleep(slot * STAGGER_NS);
    }

    // ---- prologue: init both state slots, prefetch first row ----
    if (tid == 0) {
        sh_maxbits[0] = 0u; sh_maxbits[1] = 0u;
        sh_cnt[0] = 0;      sh_cnt[1] = 0;
        sh_sum[0] = 0.0f;   sh_sum[1] = 0.0f;
    }
    int r0 = blockIdx.x;
    if (r0 < rows) {
        const float4* g = reinterpret_cast<const float4*>(x + (size_t)r0 * N_COLS);
        uint32_t s = (uint32_t)__cvta_generic_to_shared(&buf[0][0]);
#pragma unroll
        for (int k = 0; k < 4; k++) {
            uint32_t saddr = s + (uint32_t)(tid + k * THREADS) * 16u;
            asm volatile("cp.async.cg.shared.global [%0], [%1], 16;\n"
                         :: "r"(saddr), "l"(g + tid + k * THREADS));
        }
    }
    asm volatile("cp.async.commit_group;\n" ::: "memory");

    int p = 0;
    for (int r = r0; r < rows; r += stride, p ^= 1) {
        // ---- prefetch next row into buf[p^1] (overlaps this row's tau) ----
        const int rn = r + stride;
        if (rn < rows) {
            const float4* g = reinterpret_cast<const float4*>(x + (size_t)rn * N_COLS);
            uint32_t s = (uint32_t)__cvta_generic_to_shared(&buf[p ^ 1][0]);
#pragma unroll
            for (int k = 0; k < 4; k++) {
                uint32_t saddr = s + (uint32_t)(tid + k * THREADS) * 16u;
                asm volatile("cp.async.cg.shared.global [%0], [%1], 16;\n"
                             :: "r"(saddr), "l"(g + tid + k * THREADS));
            }
        }
        asm volatile("cp.async.commit_group;\n" ::: "memory");

        // wait for buf[p] (older group), leave the prefetch in flight
        asm volatile("cp.async.wait_group 1;\n" ::: "memory");
        __syncthreads();                                     // B1

        // reset the OTHER parity's state for its next use; every previous
        // reader of slot p^1 passed B1, every future writer is behind B2.
        if (tid == 0) {
            sh_maxbits[p ^ 1] = 0u;
            sh_cnt[p ^ 1] = 0;
            sh_sum[p ^ 1] = 0.0f;
        }

        const float4* b = reinterpret_cast<const float4*>(&buf[p][0]);

        // ---- single shared read: row into registers; REDUX warp max ----
        float4 v[4];
        float m = -FLT_MAX;
#pragma unroll
        for (int k = 0; k < 4; k++) {
            v[k] = b[tid + k * THREADS];
            m = fmaxf(m, fmaxf(fmaxf(v[k].x, v[k].y), fmaxf(v[k].z, v[k].w)));
        }
        unsigned we = __reduce_max_sync(0xffffffffu, enc_f(m));
        if (lane == 0) atomicMax(&sh_maxbits[p], we);
        __syncthreads();                                     // B2

        const float thresh = dec_f(sh_maxbits[p]) - 1.0f;   // tau* >= thresh

        // ---- gather candidates + fused Michelot iteration 1 (S, C) ----
        float s_part = 0.0f;
#pragma unroll
        for (int k = 0; k < 4; k++) {
            float vals[4] = {v[k].x, v[k].y, v[k].z, v[k].w};
#pragma unroll
            for (int j = 0; j < 4; j++) {
                if (vals[j] > thresh) {
                    s_part += vals[j];
                    int q = atomicAdd(&sh_cnt[p], 1);
                    if (q < CAND_CAP) cand[q] = vals[j];
                }
            }
        }
#pragma unroll
        for (int o = 16; o > 0; o >>= 1)
            s_part += __shfl_xor_sync(0xffffffffu, s_part, o);
        if (lane == 0) atomicAdd(&sh_sum[p], s_part);
        __syncthreads();                                     // B3

        // ---- warp 0 only: residual Michelot (usually 1 short iteration) ----
        if (wid == 0) {
            const int   C = sh_cnt[p];                 // exact even on overflow
            const float S = sh_sum[p];                 // exact even on overflow
            const float* src = cand;
            int nn = C;
            if (C > CAND_CAP) { nn = N_COLS; src = &buf[p][0]; }  // rare, exact
            float t = (S - 1.0f) / (float)C;           // Michelot iterate 1
            int c_prev = C;
            for (;;) {
                float s = 0.0f;
                int   c = 0;
                for (int i = lane; i < nn; i += 32) {
                    float z = src[i];
                    if (z > t) { s += z; c++; }
                }
#pragma unroll
                for (int o = 16; o > 0; o >>= 1)
                    s += __shfl_xor_sync(0xffffffffu, s, o);
                c = __reduce_add_sync(0xffffffffu, c);
                if (c == c_prev) break;        // support stabilized -> exact tau
                t = (s - 1.0f) / (float)c;     // c >= 1 (rowmax in support)
                c_prev = c;
            }
            if (lane == 0) sh_tau = t;
        }
        __syncthreads();                                     // B4
        const float tau = sh_tau;

        // ---- output straight from registers, streaming stores ----
        float4* orow = reinterpret_cast<float4*>(out + (size_t)r * N_COLS);
#pragma unroll
        for (int k = 0; k < 4; k++) {
            float4 o;
            o.x = fmaxf(v[k].x - tau, 0.0f);
            o.y = fmaxf(v[k].y - tau, 0.0f);
            o.z = fmaxf(v[k].z - tau, 0.0f);
            o.w = fmaxf(v[k].w - tau, 0.0f);
            __stcs(&orow[tid + k * THREADS], o);
        }
    }
}

extern "C" void kernel_launch(void* const* d_in, const int* in_sizes, int n_in,
                              void* d_out, int out_size) {
    const float* x = (const float*)d_in[0];
    float* out = (float*)d_out;
    const int rows = in_sizes[0] / N_COLS;   // 16384
    sparsemax_kernel<<<NBLOCKS, THREADS>>>(x, out, rows);
}